// round 12
// baseline (speedup 1.0000x reference)
#include <cuda_runtime.h>
#include <cuda_bf16.h>

// out = x + total, total = n*(n-1)/2 if n>1 else 0, n = trunc(sum(x)),
// x: 8192x8192 fp32 (64M elems, 256MB).
//
// R11 post-mortem applied:
//  - reduce reverted to R10 shape (740 CTAs @ clamp 5, MLP=4 — measured best).
//  - REAL PDL overlap: every reduce CTA calls
//    cudaTriggerProgrammaticLaunchCompletion() as soon as its contribution is
//    done (last CTA triggers after writing g_total). The add's
//    cudaGridDependencySynchronize() releases when all CTAs have triggered —
//    before full grid drain — so the finalize tail and inter-grid gap overlap
//    with the add's launch + prelude loads.
//  - add kept: 4 float4/thread, __ldcs prelude before the sync, __stcs stores.

#define NTHREADS 256
#define RED_BLOCKS 740      // 148 SMs * 5 CTAs — one exact wave

__device__ double g_partials[RED_BLOCKS];
__device__ float g_total;
__device__ unsigned int g_arrive;   // zero-init; finisher resets each launch

__global__ __launch_bounds__(NTHREADS, 5)
void reduce_kernel(const float4* __restrict__ x4, long long n4) {
    float a0 = 0.f, a1 = 0.f, a2 = 0.f, a3 = 0.f;
    const long long stride = (long long)RED_BLOCKS * NTHREADS;
    const long long tid = (long long)blockIdx.x * NTHREADS + threadIdx.x;
    const long long niter = (n4 + stride - 1) / stride;

    long long j = niter - 1;
    // top (possibly partial) chunk; walk BACKWARD so L2 ends holding x's front
    {
        long long i = j * stride + tid;
        if (i < n4) {
            float4 v = x4[i];
            a0 += v.x; a1 += v.y; a2 += v.z; a3 += v.w;
        }
        j--;
    }
    for (; j >= 3; j -= 4) {
        float4 v0 = x4[(j    ) * stride + tid];
        float4 v1 = x4[(j - 1) * stride + tid];
        float4 v2 = x4[(j - 2) * stride + tid];
        float4 v3 = x4[(j - 3) * stride + tid];
        a0 += v0.x; a1 += v0.y; a2 += v0.z; a3 += v0.w;
        a0 += v1.x; a1 += v1.y; a2 += v1.z; a3 += v1.w;
        a0 += v2.x; a1 += v2.y; a2 += v2.z; a3 += v2.w;
        a0 += v3.x; a1 += v3.y; a2 += v3.z; a3 += v3.w;
    }
    for (; j >= 0; j--) {
        float4 v = x4[j * stride + tid];
        a0 += v.x; a1 += v.y; a2 += v.z; a3 += v.w;
    }
    double acc = ((double)a0 + (double)a1) + ((double)a2 + (double)a3);

    __shared__ double s[NTHREADS];
    s[threadIdx.x] = acc;
    __syncthreads();
    #pragma unroll
    for (int off = NTHREADS / 2; off > 0; off >>= 1) {
        if (threadIdx.x < off) s[threadIdx.x] += s[threadIdx.x + off];
        __syncthreads();
    }

    __shared__ int is_last;
    if (threadIdx.x == 0) {
        g_partials[blockIdx.x] = s[0];
        __threadfence();                       // partial visible GPU-wide
        unsigned int prev = atomicAdd(&g_arrive, 1u);
        is_last = (prev == RED_BLOCKS - 1);
        if (is_last) atomicExch(&g_arrive, 0u);  // reset for next graph replay
    }
    __syncthreads();

    if (!is_last) {
        // contribution done & visible -> let the dependent grid proceed
        cudaTriggerProgrammaticLaunchCompletion();
        return;
    }

    // Last-arriving CTA finalizes in a FIXED order -> deterministic result
    // regardless of which CTA is last.
    {
        double acc2 = 0.0;
        #pragma unroll
        for (int i = threadIdx.x; i < RED_BLOCKS; i += NTHREADS)
            acc2 += g_partials[i];
        s[threadIdx.x] = acc2;
        __syncthreads();
        #pragma unroll
        for (int off = NTHREADS / 2; off > 0; off >>= 1) {
            if (threadIdx.x < off) s[threadIdx.x] += s[threadIdx.x + off];
            __syncthreads();
        }
        if (threadIdx.x == 0) {
            double total_sum = s[0];
            double nn = trunc(total_sum);   // int() truncates toward zero
            g_total = (float)((nn > 1.0) ? nn * (nn - 1.0) * 0.5 : 0.0);
            __threadfence();                // g_total visible before trigger
        }
        __syncthreads();
        cudaTriggerProgrammaticLaunchCompletion();
    }
}

// Non-persistent streaming add, 4 float4/thread, PDL-overlapped:
// all loads issue before the grid-dependency sync (read-only, no hazard),
// g_total is read after it.
__global__ __launch_bounds__(NTHREADS)
void add_kernel(const float4* __restrict__ x4, float4* __restrict__ o4,
                long long n4) {
    const long long base = (long long)blockIdx.x * (4 * NTHREADS) + threadIdx.x;
    const long long i0 = base;
    const long long i1 = base + NTHREADS;
    const long long i2 = base + 2 * NTHREADS;
    const long long i3 = base + 3 * NTHREADS;

    float4 v0, v1, v2, v3;
    bool p0 = i0 < n4, p1 = i1 < n4, p2 = i2 < n4, p3 = i3 < n4;
    if (p0) v0 = __ldcs(&x4[i0]);
    if (p1) v1 = __ldcs(&x4[i1]);
    if (p2) v2 = __ldcs(&x4[i2]);
    if (p3) v3 = __ldcs(&x4[i3]);

    cudaGridDependencySynchronize();   // releases once all reduce CTAs trigger

    const float t = g_total;
    if (p0) { v0.x += t; v0.y += t; v0.z += t; v0.w += t; __stcs(&o4[i0], v0); }
    if (p1) { v1.x += t; v1.y += t; v1.z += t; v1.w += t; __stcs(&o4[i1], v1); }
    if (p2) { v2.x += t; v2.y += t; v2.z += t; v2.w += t; __stcs(&o4[i2], v2); }
    if (p3) { v3.x += t; v3.y += t; v3.z += t; v3.w += t; __stcs(&o4[i3], v3); }
}

extern "C" void kernel_launch(void* const* d_in, const int* in_sizes, int n_in,
                              void* d_out, int out_size) {
    const float* x = (const float*)d_in[0];
    float* out = (float*)d_out;
    long long n = (long long)in_sizes[0];     // 67108864, divisible by 4
    long long n4 = n / 4;                     // 16777216

    reduce_kernel<<<RED_BLOCKS, NTHREADS>>>((const float4*)x, n4);

    long long add_blocks = (n4 + 4 * NTHREADS - 1) / (4 * NTHREADS);  // 16384

    cudaLaunchConfig_t cfg = {};
    cfg.gridDim = dim3((unsigned)add_blocks, 1, 1);
    cfg.blockDim = dim3(NTHREADS, 1, 1);
    cfg.dynamicSmemBytes = 0;
    cfg.stream = 0;
    cudaLaunchAttribute attr[1];
    attr[0].id = cudaLaunchAttributeProgrammaticStreamSerialization;
    attr[0].val.programmaticStreamSerializationAllowed = 1;
    cfg.attrs = attr;
    cfg.numAttrs = 1;
    cudaLaunchKernelEx(&cfg, add_kernel, (const float4*)x, (float4*)out, n4);
}